// round 1
// baseline (speedup 1.0000x reference)
#include <cuda_runtime.h>

#define Bb 4
#define Tt 2048
#define Cc 1024
#define Hh 16
#define HDm 64

// Scratch (allocation-free rule: __device__ globals)
__device__ float g_qkv[(size_t)Bb * Tt * 3 * Cc];  // [B*T, 3C]
__device__ float g_y[(size_t)Bb * Tt * Cc];        // [B*T, C] attention output

// ---------------------------------------------------------------------------
// Tiled SGEMM: C[M,N] = A[M,K] @ B[K,N] + bias[N]
// BM=BN=128, BK=8, 256 threads, 8x8 micro-tile per thread.
// M,N divisible by 128; K divisible by 8 (true for all our shapes).
// ---------------------------------------------------------------------------
template <int Mdim, int Ndim, int Kdim>
__global__ __launch_bounds__(256)
void sgemm_bias(const float* __restrict__ A, const float* __restrict__ Bw,
                const float* __restrict__ bias, float* __restrict__ Co)
{
    __shared__ float As[8][128];   // transposed A tile: As[k][m]
    __shared__ float Bs[8][128];   // Bs[k][n]

    const int tid  = threadIdx.x;
    const int tx   = tid & 15;     // 0..15 -> N micro position
    const int ty   = tid >> 4;     // 0..15 -> M micro position
    const int brow = blockIdx.y * 128;
    const int bcol = blockIdx.x * 128;

    const int arow = tid >> 1;           // 0..127
    const int akc  = (tid & 1) * 4;      // 0 or 4
    const int bkr  = tid >> 5;           // 0..7
    const int bnc  = (tid & 31) * 4;     // 0..124

    const float* Ap = A + (size_t)(brow + arow) * Kdim + akc;
    const float* Bp = Bw + (size_t)bkr * Ndim + bcol + bnc;

    float acc[8][8];
#pragma unroll
    for (int i = 0; i < 8; i++)
#pragma unroll
        for (int j = 0; j < 8; j++) acc[i][j] = 0.f;

    for (int k0 = 0; k0 < Kdim; k0 += 8) {
        float4 a4 = *(const float4*)Ap;
        As[akc + 0][arow] = a4.x;
        As[akc + 1][arow] = a4.y;
        As[akc + 2][arow] = a4.z;
        As[akc + 3][arow] = a4.w;
        *(float4*)&Bs[bkr][bnc] = *(const float4*)Bp;
        __syncthreads();

#pragma unroll
        for (int k = 0; k < 8; k++) {
            float ar[8], br[8];
            *(float4*)&ar[0] = *(const float4*)&As[k][ty * 8];
            *(float4*)&ar[4] = *(const float4*)&As[k][ty * 8 + 4];
            *(float4*)&br[0] = *(const float4*)&Bs[k][tx * 8];
            *(float4*)&br[4] = *(const float4*)&Bs[k][tx * 8 + 4];
#pragma unroll
            for (int i = 0; i < 8; i++)
#pragma unroll
                for (int j = 0; j < 8; j++)
                    acc[i][j] += ar[i] * br[j];
        }
        __syncthreads();

        Ap += 8;
        Bp += (size_t)8 * Ndim;
    }

#pragma unroll
    for (int i = 0; i < 8; i++) {
        float* crow = Co + (size_t)(brow + ty * 8 + i) * Ndim + bcol + tx * 8;
        const float* bp = bias + bcol + tx * 8;
#pragma unroll
        for (int j = 0; j < 8; j += 4) {
            float4 w;
            w.x = acc[i][j + 0] + bp[j + 0];
            w.y = acc[i][j + 1] + bp[j + 1];
            w.z = acc[i][j + 2] + bp[j + 2];
            w.w = acc[i][j + 3] + bp[j + 3];
            *(float4*)(crow + j) = w;
        }
    }
}

// ---------------------------------------------------------------------------
// Flash attention (causal), fp32.
// Block: 128 threads, one 64-row Q tile for one (b,h).
// Loops over KV tiles of 64 up to the causal limit, online softmax.
// Thread micro-tile: 4 query rows (rg=tid>>3) x 8 kv cols / 8 hd cols (cg=tid&7).
// qkv layout: [B*T, 3C]; q at col h*64, k at C + h*64, v at 2C + h*64.
// Output y: [B*T, C].
// ---------------------------------------------------------------------------
__global__ __launch_bounds__(128)
void flash_attn(const float* __restrict__ qkv, float* __restrict__ y)
{
    extern __shared__ float sm[];
    float* qs = sm;                    // [64][64] transposed: qs[d][row]
    float* ks = sm + 4096;             // [64][64] transposed: ks[d][col]
    float* vs = sm + 8192;             // [64][68]: vs[kv][d], padded
    float* ps = sm + 8192 + 64 * 68;   // [64][65]: ps[kv][row], padded

    const int tid = threadIdx.x;
    const int rg  = tid >> 3;  // 0..15 -> rows rg*4 .. rg*4+3
    const int cg  = tid & 7;   // 0..7  -> cols cg*8 .. cg*8+7
    const int qt  = blockIdx.x;     // query tile 0..31
    const int bh  = blockIdx.y;     // 0..63
    const int b   = bh >> 4;
    const int h   = bh & 15;

    const size_t rs = 3 * Cc;
    const float* base = qkv + (size_t)b * Tt * rs + (size_t)h * HDm;

    const int lr = tid & 63;          // tile row this thread loads
    const int dh = (tid >> 6) * 32;   // which 32-wide d half

    // ---- load Q tile, transposed + pre-scaled by 1/sqrt(64) ----
    {
        const float* qr = base + (size_t)(qt * 64 + lr) * rs + dh;
#pragma unroll
        for (int d = 0; d < 32; d += 4) {
            float4 v = *(const float4*)(qr + d);
            qs[(dh + d + 0) * 64 + lr] = v.x * 0.125f;
            qs[(dh + d + 1) * 64 + lr] = v.y * 0.125f;
            qs[(dh + d + 2) * 64 + lr] = v.z * 0.125f;
            qs[(dh + d + 3) * 64 + lr] = v.w * 0.125f;
        }
    }

    float o[4][8];
#pragma unroll
    for (int i = 0; i < 4; i++)
#pragma unroll
        for (int j = 0; j < 8; j++) o[i][j] = 0.f;
    float m[4] = {-1e30f, -1e30f, -1e30f, -1e30f};
    float l[4] = {0.f, 0.f, 0.f, 0.f};

    __syncthreads();

    for (int kt = 0; kt <= qt; kt++) {
        // ---- load K (transposed) and V (natural, padded) tiles ----
        {
            const float* kr = base + Cc + (size_t)(kt * 64 + lr) * rs + dh;
            const float* vr = base + 2 * Cc + (size_t)(kt * 64 + lr) * rs + dh;
#pragma unroll
            for (int d = 0; d < 32; d += 4) {
                float4 k4 = *(const float4*)(kr + d);
                ks[(dh + d + 0) * 64 + lr] = k4.x;
                ks[(dh + d + 1) * 64 + lr] = k4.y;
                ks[(dh + d + 2) * 64 + lr] = k4.z;
                ks[(dh + d + 3) * 64 + lr] = k4.w;
                *(float4*)&vs[lr * 68 + dh + d] = *(const float4*)(vr + d);
            }
        }
        __syncthreads();

        // ---- S = Q K^T (4x8 per thread) ----
        float s[4][8];
#pragma unroll
        for (int i = 0; i < 4; i++)
#pragma unroll
            for (int j = 0; j < 8; j++) s[i][j] = 0.f;

#pragma unroll 8
        for (int kk = 0; kk < 64; kk++) {
            float4 q4 = *(const float4*)&qs[kk * 64 + rg * 4];
            float4 ka = *(const float4*)&ks[kk * 64 + cg * 8];
            float4 kb = *(const float4*)&ks[kk * 64 + cg * 8 + 4];
            float qa[4] = {q4.x, q4.y, q4.z, q4.w};
            float kv[8] = {ka.x, ka.y, ka.z, ka.w, kb.x, kb.y, kb.z, kb.w};
#pragma unroll
            for (int i = 0; i < 4; i++)
#pragma unroll
                for (int j = 0; j < 8; j++)
                    s[i][j] += qa[i] * kv[j];
        }

        // ---- causal mask (diagonal tile only) ----
        if (kt == qt) {
#pragma unroll
            for (int i = 0; i < 4; i++) {
                int r = rg * 4 + i;
#pragma unroll
                for (int j = 0; j < 8; j++)
                    if (cg * 8 + j > r) s[i][j] = -1e30f;
            }
        }

        // ---- online softmax update ----
#pragma unroll
        for (int i = 0; i < 4; i++) {
            float mx = s[i][0];
#pragma unroll
            for (int j = 1; j < 8; j++) mx = fmaxf(mx, s[i][j]);
            mx = fmaxf(mx, __shfl_xor_sync(0xffffffffu, mx, 1));
            mx = fmaxf(mx, __shfl_xor_sync(0xffffffffu, mx, 2));
            mx = fmaxf(mx, __shfl_xor_sync(0xffffffffu, mx, 4));

            float mn  = fmaxf(m[i], mx);
            float fac = __expf(m[i] - mn);
            float sum = 0.f;
#pragma unroll
            for (int j = 0; j < 8; j++) {
                float p = __expf(s[i][j] - mn);
                s[i][j] = p;
                sum += p;
            }
            sum += __shfl_xor_sync(0xffffffffu, sum, 1);
            sum += __shfl_xor_sync(0xffffffffu, sum, 2);
            sum += __shfl_xor_sync(0xffffffffu, sum, 4);

            l[i] = l[i] * fac + sum;
            m[i] = mn;
#pragma unroll
            for (int j = 0; j < 8; j++) {
                o[i][j] *= fac;
                ps[(cg * 8 + j) * 65 + rg * 4 + i] = s[i][j];  // transposed store
            }
        }
        __syncthreads();

        // ---- O += P V (4 rows x 8 hd cols per thread) ----
#pragma unroll 8
        for (int kk = 0; kk < 64; kk++) {
            float pp[4];
            pp[0] = ps[kk * 65 + rg * 4 + 0];
            pp[1] = ps[kk * 65 + rg * 4 + 1];
            pp[2] = ps[kk * 65 + rg * 4 + 2];
            pp[3] = ps[kk * 65 + rg * 4 + 3];
            float4 va = *(const float4*)&vs[kk * 68 + cg * 8];
            float4 vb = *(const float4*)&vs[kk * 68 + cg * 8 + 4];
            float vv[8] = {va.x, va.y, va.z, va.w, vb.x, vb.y, vb.z, vb.w};
#pragma unroll
            for (int i = 0; i < 4; i++)
#pragma unroll
                for (int j = 0; j < 8; j++)
                    o[i][j] += pp[i] * vv[j];
        }
        __syncthreads();
    }

    // ---- epilogue: O / l -> y[B*T, C] ----
#pragma unroll
    for (int i = 0; i < 4; i++) {
        float inv = 1.0f / l[i];
        float* yr = y + (size_t)(b * Tt + qt * 64 + rg * 4 + i) * Cc + h * HDm + cg * 8;
        float4 w0, w1;
        w0.x = o[i][0] * inv; w0.y = o[i][1] * inv;
        w0.z = o[i][2] * inv; w0.w = o[i][3] * inv;
        w1.x = o[i][4] * inv; w1.y = o[i][5] * inv;
        w1.z = o[i][6] * inv; w1.w = o[i][7] * inv;
        *(float4*)yr = w0;
        *(float4*)(yr + 4) = w1;
    }
}

// ---------------------------------------------------------------------------
extern "C" void kernel_launch(void* const* d_in, const int* in_sizes, int n_in,
                              void* d_out, int out_size)
{
    const float* x      = (const float*)d_in[0];
    const float* w_attn = (const float*)d_in[1];
    const float* b_attn = (const float*)d_in[2];
    const float* w_proj = (const float*)d_in[3];
    const float* b_proj = (const float*)d_in[4];
    float* out = (float*)d_out;

    float* qkv = nullptr;
    float* yb  = nullptr;
    cudaGetSymbolAddress((void**)&qkv, g_qkv);
    cudaGetSymbolAddress((void**)&yb, g_y);

    // 1) QKV GEMM: [8192,1024] @ [1024,3072] + bias
    sgemm_bias<Bb * Tt, 3 * Cc, Cc>
        <<<dim3((3 * Cc) / 128, (Bb * Tt) / 128), 256>>>(x, w_attn, b_attn, qkv);

    // 2) Causal flash attention
    constexpr int FLASH_SMEM = (4096 + 4096 + 64 * 68 + 64 * 65) * 4;  // 66816 B
    cudaFuncSetAttribute(flash_attn, cudaFuncAttributeMaxDynamicSharedMemorySize,
                         FLASH_SMEM);
    flash_attn<<<dim3(Tt / 64, Bb * Hh), 128, FLASH_SMEM>>>(qkv, yb);

    // 3) Output projection: [8192,1024] @ [1024,1024] + bias
    sgemm_bias<Bb * Tt, Cc, Cc>
        <<<dim3(Cc / 128, (Bb * Tt) / 128), 256>>>(yb, w_proj, b_proj, out);
}

// round 3
// speedup vs baseline: 1.3607x; 1.3607x over previous
#include <cuda_runtime.h>
#include <cuda_bf16.h>
#include <cstdint>

#define Bb 4
#define Tt 2048
#define Cc 1024
#define Hh 16
#define HDm 64

// ---------------- scratch (__device__ globals; allocation-free rule) ---------
__device__ float g_qkv[(size_t)Bb * Tt * 3 * Cc];       // [8192, 3072]
__device__ float g_y[(size_t)Bb * Tt * Cc];             // [8192, 1024]
__device__ __nv_bfloat16 g_xhi[(size_t)Bb * Tt * Cc];
__device__ __nv_bfloat16 g_xlo[(size_t)Bb * Tt * Cc];
__device__ __nv_bfloat16 g_yhi[(size_t)Bb * Tt * Cc];
__device__ __nv_bfloat16 g_ylo[(size_t)Bb * Tt * Cc];
__device__ __nv_bfloat16 g_wahi[(size_t)3 * Cc * Cc];   // [3072, 1024] (N,K)
__device__ __nv_bfloat16 g_walo[(size_t)3 * Cc * Cc];
__device__ __nv_bfloat16 g_wphi[(size_t)Cc * Cc];       // [1024, 1024] (N,K)
__device__ __nv_bfloat16 g_wplo[(size_t)Cc * Cc];

// ---------------- helpers ------------------------------------------------
__device__ __forceinline__ uint32_t smem_u32(const void* p) {
    return (uint32_t)__cvta_generic_to_shared(p);
}
__device__ __forceinline__ void cp_async16(uint32_t dst, const void* src) {
    asm volatile("cp.async.cg.shared.global [%0], [%1], 16;\n"
                 :: "r"(dst), "l"(src));
}
#define CP_COMMIT() asm volatile("cp.async.commit_group;\n" ::: "memory")
#define CP_WAIT1()  asm volatile("cp.async.wait_group 1;\n" ::: "memory")
#define CP_WAIT0()  asm volatile("cp.async.wait_group 0;\n" ::: "memory")

// ldmatrix x4: loads 4 8x8 b16 matrices
#define LDSM4(r0, r1, r2, r3, addr) \
    asm volatile("ldmatrix.sync.aligned.m8n8.x4.shared.b16 {%0,%1,%2,%3}, [%4];" \
                 : "=r"(r0), "=r"(r1), "=r"(r2), "=r"(r3) : "r"(addr))

// mma m16n8k16 row.col f32 <- bf16 x bf16 + f32
#define MMA16816(d, a, b) \
    asm volatile("mma.sync.aligned.m16n8k16.row.col.f32.bf16.bf16.f32 " \
                 "{%0,%1,%2,%3}, {%4,%5,%6,%7}, {%8,%9}, {%0,%1,%2,%3};" \
                 : "+f"((d)[0]), "+f"((d)[1]), "+f"((d)[2]), "+f"((d)[3]) \
                 : "r"((a)[0]), "r"((a)[1]), "r"((a)[2]), "r"((a)[3]), \
                   "r"((b)[0]), "r"((b)[1]))

// ---------------- conversion kernels -----------------------------------------
__global__ void split_rows(const float4* __restrict__ in,
                           __nv_bfloat16* __restrict__ hi,
                           __nv_bfloat16* __restrict__ lo, int n4)
{
    int i = blockIdx.x * blockDim.x + threadIdx.x;
    if (i >= n4) return;
    float4 v = in[i];
    float vv[4] = {v.x, v.y, v.z, v.w};
#pragma unroll
    for (int j = 0; j < 4; j++) {
        __nv_bfloat16 h = __float2bfloat16(vv[j]);
        float hf = __bfloat162float(h);
        hi[i * 4 + j] = h;
        lo[i * 4 + j] = __float2bfloat16(vv[j] - hf);
    }
}

// in: [K, N] row-major fp32 -> out hi/lo: [N, K] row-major bf16
__global__ void split_transpose(const float* __restrict__ in,
                                __nv_bfloat16* __restrict__ hi,
                                __nv_bfloat16* __restrict__ lo, int K, int N)
{
    __shared__ float t[32][33];
    int x = blockIdx.x * 32 + threadIdx.x;  // N
    int y = blockIdx.y * 32 + threadIdx.y;  // K
#pragma unroll
    for (int j = 0; j < 32; j += 8)
        t[threadIdx.y + j][threadIdx.x] = in[(size_t)(y + j) * N + x];
    __syncthreads();
    int xo = blockIdx.y * 32 + threadIdx.x;  // K
    int yo = blockIdx.x * 32 + threadIdx.y;  // N
#pragma unroll
    for (int j = 0; j < 32; j += 8) {
        float v = t[threadIdx.x][threadIdx.y + j];
        __nv_bfloat16 h = __float2bfloat16(v);
        float hf = __bfloat162float(h);
        size_t idx = (size_t)(yo + j) * K + xo;
        hi[idx] = h;
        lo[idx] = __float2bfloat16(v - hf);
    }
}

// ---------------- mma.sync split-bf16 GEMM -----------------------------------
// C[M,N] = (Ahi+Alo)[M,K] @ (Bhi+Blo)[N,K]^T + bias[N]  (3-term bf16 split)
// CTA tile 128x128, 256 threads (8 warps, 2x4), warp tile 64x32.
// K chunk 32, 3-stage cp.async pipeline.
// Smem per stage: Ahi|Alo|Bhi|Blo, each 128 rows x 40 bf16 (80B padded rows).
template <int Mdim, int Ndim, int Kdim>
__global__ __launch_bounds__(256)
void gemm_mma(const __nv_bfloat16* __restrict__ Ahi,
              const __nv_bfloat16* __restrict__ Alo,
              const __nv_bfloat16* __restrict__ Bhi,
              const __nv_bfloat16* __restrict__ Blo,
              const float* __restrict__ bias, float* __restrict__ C)
{
    constexpr int NCHUNK = Kdim / 32;
    constexpr uint32_t STAGE = 40960;   // 4 * 128 * 80
    constexpr uint32_t MATB = 10240;    // 128 * 80

    extern __shared__ char smem[];
    const uint32_t sbase = smem_u32(smem);

    const int tid  = threadIdx.x;
    const int wid  = tid >> 5;
    const int lane = tid & 31;
    const int m0 = blockIdx.y * 128;
    const int n0 = blockIdx.x * 128;
    const int wm = (wid >> 2) * 64;   // warp row offset in tile
    const int wn = (wid & 3) * 32;    // warp col offset in tile

    // ldmatrix per-lane address components
    const int arow = lane & 15;
    const int ak8  = (lane >> 4) * 8;              // A k offset (elems)
    const int bn   = ((lane >> 4) << 3) + (lane & 7);  // B n offset within 16
    const int bk8  = lane & 8;                     // B k offset (elems)

    auto load_chunk = [&](int c, int st) {
        const int k0 = c * 32;
        const uint32_t sb = sbase + (uint32_t)st * STAGE;
#pragma unroll
        for (int t = 0; t < 8; t++) {
            int i = tid + t * 256;            // 0..2047
            int mat = i >> 9;                 // 0:Ahi 1:Alo 2:Bhi 3:Blo
            int rem = i & 511;
            int row = rem >> 2, seg = rem & 3;
            uint32_t dst = sb + (uint32_t)mat * MATB + row * 80 + seg * 16;
            const __nv_bfloat16* src;
            if (mat == 0)      src = Ahi + (size_t)(m0 + row) * Kdim + k0 + seg * 8;
            else if (mat == 1) src = Alo + (size_t)(m0 + row) * Kdim + k0 + seg * 8;
            else if (mat == 2) src = Bhi + (size_t)(n0 + row) * Kdim + k0 + seg * 8;
            else               src = Blo + (size_t)(n0 + row) * Kdim + k0 + seg * 8;
            cp_async16(dst, src);
        }
    };

    float acc[4][4][4];
#pragma unroll
    for (int i = 0; i < 4; i++)
#pragma unroll
        for (int j = 0; j < 4; j++)
#pragma unroll
            for (int k = 0; k < 4; k++) acc[i][j][k] = 0.f;

    load_chunk(0, 0); CP_COMMIT();
    if (NCHUNK > 1) { load_chunk(1, 1); }
    CP_COMMIT();

    for (int c = 0; c < NCHUNK; c++) {
        CP_WAIT1();
        __syncthreads();
        if (c + 2 < NCHUNK) load_chunk(c + 2, (c + 2) % 3);
        CP_COMMIT();

        const uint32_t sb = sbase + (uint32_t)(c % 3) * STAGE;
        const uint32_t sAh = sb, sAl = sb + MATB, sBh = sb + 2 * MATB, sBl = sb + 3 * MATB;

        uint32_t ah[4][4], al[4][4], bh[4][2], bl[4][2];
#pragma unroll
        for (int ks = 0; ks < 2; ks++) {
            const uint32_t kb = ks * 32;  // ks*16 elems * 2B
#pragma unroll
            for (int mf = 0; mf < 4; mf++) {
                uint32_t ra = (uint32_t)(wm + mf * 16 + arow) * 80 + kb + ak8 * 2;
                LDSM4(ah[mf][0], ah[mf][1], ah[mf][2], ah[mf][3], sAh + ra);
                LDSM4(al[mf][0], al[mf][1], al[mf][2], al[mf][3], sAl + ra);
            }
#pragma unroll
            for (int np = 0; np < 2; np++) {
                uint32_t rb = (uint32_t)(wn + np * 16 + bn) * 80 + kb + bk8 * 2;
                LDSM4(bh[np * 2][0], bh[np * 2][1], bh[np * 2 + 1][0], bh[np * 2 + 1][1],
                      sBh + rb);
                LDSM4(bl[np * 2][0], bl[np * 2][1], bl[np * 2 + 1][0], bl[np * 2 + 1][1],
                      sBl + rb);
            }
#pragma unroll
            for (int mf = 0; mf < 4; mf++)
#pragma unroll
                for (int nf = 0; nf < 4; nf++) {
                    MMA16816(acc[mf][nf], ah[mf], bh[nf]);
                    MMA16816(acc[mf][nf], ah[mf], bl[nf]);
                    MMA16816(acc[mf][nf], al[mf], bh[nf]);
                }
        }
    }

    // ---- epilogue: write fp32 + bias ----
    const int r0 = lane >> 2;
    const int c0 = (lane & 3) * 2;
#pragma unroll
    for (int mf = 0; mf < 4; mf++) {
#pragma unroll
        for (int nf = 0; nf < 4; nf++) {
            int row = m0 + wm + mf * 16 + r0;
            int col = n0 + wn + nf * 8 + c0;
            float2 b2 = *(const float2*)(bias + col);
            float2 w0, w1;
            w0.x = acc[mf][nf][0] + b2.x;
            w0.y = acc[mf][nf][1] + b2.y;
            w1.x = acc[mf][nf][2] + b2.x;
            w1.y = acc[mf][nf][3] + b2.y;
            *(float2*)(C + (size_t)row * Ndim + col) = w0;
            *(float2*)(C + (size_t)(row + 8) * Ndim + col) = w1;
        }
    }
}

// ---------------- flash attention (fp32 SIMT, unchanged) ---------------------
__global__ __launch_bounds__(128)
void flash_attn(const float* __restrict__ qkv, float* __restrict__ y)
{
    extern __shared__ float sm[];
    float* qs = sm;
    float* ks = sm + 4096;
    float* vs = sm + 8192;
    float* ps = sm + 8192 + 64 * 68;

    const int tid = threadIdx.x;
    const int rg  = tid >> 3;
    const int cg  = tid & 7;
    const int qt  = blockIdx.x;
    const int bh  = blockIdx.y;
    const int b   = bh >> 4;
    const int h   = bh & 15;

    const size_t rs = 3 * Cc;
    const float* basep = qkv + (size_t)b * Tt * rs + (size_t)h * HDm;

    const int lr = tid & 63;
    const int dh = (tid >> 6) * 32;

    {
        const float* qr = basep + (size_t)(qt * 64 + lr) * rs + dh;
#pragma unroll
        for (int d = 0; d < 32; d += 4) {
            float4 v = *(const float4*)(qr + d);
            qs[(dh + d + 0) * 64 + lr] = v.x * 0.125f;
            qs[(dh + d + 1) * 64 + lr] = v.y * 0.125f;
            qs[(dh + d + 2) * 64 + lr] = v.z * 0.125f;
            qs[(dh + d + 3) * 64 + lr] = v.w * 0.125f;
        }
    }

    float o[4][8];
#pragma unroll
    for (int i = 0; i < 4; i++)
#pragma unroll
        for (int j = 0; j < 8; j++) o[i][j] = 0.f;
    float m[4] = {-1e30f, -1e30f, -1e30f, -1e30f};
    float l[4] = {0.f, 0.f, 0.f, 0.f};

    __syncthreads();

    for (int kt = 0; kt <= qt; kt++) {
        {
            const float* kr = basep + Cc + (size_t)(kt * 64 + lr) * rs + dh;
            const float* vr = basep + 2 * Cc + (size_t)(kt * 64 + lr) * rs + dh;
#pragma unroll
            for (int d = 0; d < 32; d += 4) {
                float4 k4 = *(const float4*)(kr + d);
                ks[(dh + d + 0) * 64 + lr] = k4.x;
                ks[(dh + d + 1) * 64 + lr] = k4.y;
                ks[(dh + d + 2) * 64 + lr] = k4.z;
                ks[(dh + d + 3) * 64 + lr] = k4.w;
                *(float4*)&vs[lr * 68 + dh + d] = *(const float4*)(vr + d);
            }
        }
        __syncthreads();

        float s[4][8];
#pragma unroll
        for (int i = 0; i < 4; i++)
#pragma unroll
            for (int j = 0; j < 8; j++) s[i][j] = 0.f;

#pragma unroll 8
        for (int kk = 0; kk < 64; kk++) {
            float4 q4 = *(const float4*)&qs[kk * 64 + rg * 4];
            float4 ka = *(const float4*)&ks[kk * 64 + cg * 8];
            float4 kb = *(const float4*)&ks[kk * 64 + cg * 8 + 4];
            float qa[4] = {q4.x, q4.y, q4.z, q4.w};
            float kv[8] = {ka.x, ka.y, ka.z, ka.w, kb.x, kb.y, kb.z, kb.w};
#pragma unroll
            for (int i = 0; i < 4; i++)
#pragma unroll
                for (int j = 0; j < 8; j++)
                    s[i][j] += qa[i] * kv[j];
        }

        if (kt == qt) {
#pragma unroll
            for (int i = 0; i < 4; i++) {
                int r = rg * 4 + i;
#pragma unroll
                for (int j = 0; j < 8; j++)
                    if (cg * 8 + j > r) s[i][j] = -1e30f;
            }
        }

#pragma unroll
        for (int i = 0; i < 4; i++) {
            float mx = s[i][0];
#pragma unroll
            for (int j = 1; j < 8; j++) mx = fmaxf(mx, s[i][j]);
            mx = fmaxf(mx, __shfl_xor_sync(0xffffffffu, mx, 1));
            mx = fmaxf(mx, __shfl_xor_sync(0xffffffffu, mx, 2));
            mx = fmaxf(mx, __shfl_xor_sync(0xffffffffu, mx, 4));

            float mn  = fmaxf(m[i], mx);
            float fac = __expf(m[i] - mn);
            float sum = 0.f;
#pragma unroll
            for (int j = 0; j < 8; j++) {
                float p = __expf(s[i][j] - mn);
                s[i][j] = p;
                sum += p;
            }
            sum += __shfl_xor_sync(0xffffffffu, sum, 1);
            sum += __shfl_xor_sync(0xffffffffu, sum, 2);
            sum += __shfl_xor_sync(0xffffffffu, sum, 4);

            l[i] = l[i] * fac + sum;
            m[i] = mn;
#pragma unroll
            for (int j = 0; j < 8; j++) {
                o[i][j] *= fac;
                ps[(cg * 8 + j) * 65 + rg * 4 + i] = s[i][j];
            }
        }
        __syncthreads();

#pragma unroll 8
        for (int kk = 0; kk < 64; kk++) {
            float pp[4];
            pp[0] = ps[kk * 65 + rg * 4 + 0];
            pp[1] = ps[kk * 65 + rg * 4 + 1];
            pp[2] = ps[kk * 65 + rg * 4 + 2];
            pp[3] = ps[kk * 65 + rg * 4 + 3];
            float4 va = *(const float4*)&vs[kk * 68 + cg * 8];
            float4 vb = *(const float4*)&vs[kk * 68 + cg * 8 + 4];
            float vv[8] = {va.x, va.y, va.z, va.w, vb.x, vb.y, vb.z, vb.w};
#pragma unroll
            for (int i = 0; i < 4; i++)
#pragma unroll
                for (int j = 0; j < 8; j++)
                    o[i][j] += pp[i] * vv[j];
        }
        __syncthreads();
    }

#pragma unroll
    for (int i = 0; i < 4; i++) {
        float inv = 1.0f / l[i];
        float* yr = y + (size_t)(b * Tt + qt * 64 + rg * 4 + i) * Cc + h * HDm + cg * 8;
        float4 w0, w1;
        w0.x = o[i][0] * inv; w0.y = o[i][1] * inv;
        w0.z = o[i][2] * inv; w0.w = o[i][3] * inv;
        w1.x = o[i][4] * inv; w1.y = o[i][5] * inv;
        w1.z = o[i][6] * inv; w1.w = o[i][7] * inv;
        *(float4*)yr = w0;
        *(float4*)(yr + 4) = w1;
    }
}

// ---------------- launch ------------------------------------------------------
extern "C" void kernel_launch(void* const* d_in, const int* in_sizes, int n_in,
                              void* d_out, int out_size)
{
    const float* x      = (const float*)d_in[0];
    const float* w_attn = (const float*)d_in[1];
    const float* b_attn = (const float*)d_in[2];
    const float* w_proj = (const float*)d_in[3];
    const float* b_proj = (const float*)d_in[4];
    float* out = (float*)d_out;

    float *qkv, *yb;
    __nv_bfloat16 *xhi, *xlo, *yhi, *ylo, *wahi, *walo, *wphi, *wplo;
    cudaGetSymbolAddress((void**)&qkv, g_qkv);
    cudaGetSymbolAddress((void**)&yb, g_y);
    cudaGetSymbolAddress((void**)&xhi, g_xhi);
    cudaGetSymbolAddress((void**)&xlo, g_xlo);
    cudaGetSymbolAddress((void**)&yhi, g_yhi);
    cudaGetSymbolAddress((void**)&ylo, g_ylo);
    cudaGetSymbolAddress((void**)&wahi, g_wahi);
    cudaGetSymbolAddress((void**)&walo, g_walo);
    cudaGetSymbolAddress((void**)&wphi, g_wphi);
    cudaGetSymbolAddress((void**)&wplo, g_wplo);

    constexpr int GEMM_SMEM = 3 * 40960;  // 122880
    cudaFuncSetAttribute(gemm_mma<Bb * Tt, 3 * Cc, Cc>,
                         cudaFuncAttributeMaxDynamicSharedMemorySize, GEMM_SMEM);
    cudaFuncSetAttribute(gemm_mma<Bb * Tt, Cc, Cc>,
                         cudaFuncAttributeMaxDynamicSharedMemorySize, GEMM_SMEM);
    constexpr int FLASH_SMEM = (4096 + 4096 + 64 * 68 + 64 * 65) * 4;
    cudaFuncSetAttribute(flash_attn, cudaFuncAttributeMaxDynamicSharedMemorySize,
                         FLASH_SMEM);

    // 1) split inputs / weights into bf16 hi/lo
    {
        int n4 = (Bb * Tt * Cc) / 4;
        split_rows<<<(n4 + 255) / 256, 256>>>((const float4*)x, xhi, xlo, n4);
        split_transpose<<<dim3((3 * Cc) / 32, Cc / 32), dim3(32, 8)>>>(
            w_attn, wahi, walo, Cc, 3 * Cc);
        split_transpose<<<dim3(Cc / 32, Cc / 32), dim3(32, 8)>>>(
            w_proj, wphi, wplo, Cc, Cc);
    }

    // 2) QKV GEMM (mma.sync bf16 split-3): [8192,1024] @ [1024,3072]
    gemm_mma<Bb * Tt, 3 * Cc, Cc>
        <<<dim3((3 * Cc) / 128, (Bb * Tt) / 128), 256, GEMM_SMEM>>>(
            xhi, xlo, wahi, walo, b_attn, qkv);

    // 3) causal flash attention (fp32 SIMT)
    flash_attn<<<dim3(Tt / 64, Bb * Hh), 128, FLASH_SMEM>>>(qkv, yb);

    // 4) split y, then output projection
    {
        int n4 = (Bb * Tt * Cc) / 4;
        split_rows<<<(n4 + 255) / 256, 256>>>((const float4*)yb, yhi, ylo, n4);
    }
    gemm_mma<Bb * Tt, Cc, Cc>
        <<<dim3(Cc / 128, (Bb * Tt) / 128), 256, GEMM_SMEM>>>(
            yhi, ylo, wphi, wplo, b_proj, out);
}

// round 4
// speedup vs baseline: 3.0524x; 2.2433x over previous
#include <cuda_runtime.h>
#include <cuda_bf16.h>
#include <cstdint>

#define Bb 4
#define Tt 2048
#define Cc 1024
#define Hh 16
#define HDm 64

// ---------------- scratch ------------------------------------------------
__device__ __nv_bfloat16 g_qkvhi[(size_t)Bb * Tt * 3 * Cc];  // [8192, 3072]
__device__ __nv_bfloat16 g_qkvlo[(size_t)Bb * Tt * 3 * Cc];
__device__ __nv_bfloat16 g_xhi[(size_t)Bb * Tt * Cc];
__device__ __nv_bfloat16 g_xlo[(size_t)Bb * Tt * Cc];
__device__ __nv_bfloat16 g_yhi[(size_t)Bb * Tt * Cc];
__device__ __nv_bfloat16 g_ylo[(size_t)Bb * Tt * Cc];
__device__ __nv_bfloat16 g_wahi[(size_t)3 * Cc * Cc];        // [3072,1024] (N,K)
__device__ __nv_bfloat16 g_walo[(size_t)3 * Cc * Cc];
__device__ __nv_bfloat16 g_wphi[(size_t)Cc * Cc];
__device__ __nv_bfloat16 g_wplo[(size_t)Cc * Cc];

// ---------------- helpers ------------------------------------------------
__device__ __forceinline__ uint32_t smem_u32(const void* p) {
    return (uint32_t)__cvta_generic_to_shared(p);
}
__device__ __forceinline__ void cp_async16(uint32_t dst, const void* src) {
    asm volatile("cp.async.cg.shared.global [%0], [%1], 16;\n"
                 :: "r"(dst), "l"(src));
}
#define CP_COMMIT() asm volatile("cp.async.commit_group;\n" ::: "memory")
#define CP_WAIT1()  asm volatile("cp.async.wait_group 1;\n" ::: "memory")

#define LDSM4(r0, r1, r2, r3, addr) \
    asm volatile("ldmatrix.sync.aligned.m8n8.x4.shared.b16 {%0,%1,%2,%3}, [%4];" \
                 : "=r"(r0), "=r"(r1), "=r"(r2), "=r"(r3) : "r"(addr))
#define LDSM4T(r0, r1, r2, r3, addr) \
    asm volatile("ldmatrix.sync.aligned.m8n8.x4.trans.shared.b16 {%0,%1,%2,%3}, [%4];" \
                 : "=r"(r0), "=r"(r1), "=r"(r2), "=r"(r3) : "r"(addr))

#define MMA16816(d, a, b) \
    asm volatile("mma.sync.aligned.m16n8k16.row.col.f32.bf16.bf16.f32 " \
                 "{%0,%1,%2,%3}, {%4,%5,%6,%7}, {%8,%9}, {%0,%1,%2,%3};" \
                 : "+f"((d)[0]), "+f"((d)[1]), "+f"((d)[2]), "+f"((d)[3]) \
                 : "r"((a)[0]), "r"((a)[1]), "r"((a)[2]), "r"((a)[3]), \
                   "r"((b)[0]), "r"((b)[1]))
#define MMA2(d, a, bv0, bv1) \
    asm volatile("mma.sync.aligned.m16n8k16.row.col.f32.bf16.bf16.f32 " \
                 "{%0,%1,%2,%3}, {%4,%5,%6,%7}, {%8,%9}, {%0,%1,%2,%3};" \
                 : "+f"((d)[0]), "+f"((d)[1]), "+f"((d)[2]), "+f"((d)[3]) \
                 : "r"((a)[0]), "r"((a)[1]), "r"((a)[2]), "r"((a)[3]), \
                   "r"(bv0), "r"(bv1))

// pack two floats to bf16x2 (RN):  {hi: a, lo: b}
__device__ __forceinline__ uint32_t packbf2(float hi, float lo) {
    uint32_t d;
    asm("cvt.rn.bf16x2.f32 %0, %1, %2;" : "=r"(d) : "f"(hi), "f"(lo));
    return d;
}
// truncate float to bf16-representable float
__device__ __forceinline__ float truncbf(float x) {
    return __uint_as_float(__float_as_uint(x) & 0xffff0000u);
}
// pack {hi16(p1), hi16(p0)} into one u32 (truncation split, hi parts)
__device__ __forceinline__ uint32_t packhi2(float p0, float p1) {
    return __byte_perm(__float_as_uint(p0), __float_as_uint(p1), 0x7632);
}

// ---------------- conversion kernels --------------------------------------
__global__ void split_rows(const float4* __restrict__ in,
                           __nv_bfloat16* __restrict__ hi,
                           __nv_bfloat16* __restrict__ lo, int n4)
{
    int i = blockIdx.x * blockDim.x + threadIdx.x;
    if (i >= n4) return;
    float4 v = in[i];
    float vv[4] = {v.x, v.y, v.z, v.w};
#pragma unroll
    for (int j = 0; j < 4; j++) {
        __nv_bfloat16 h = __float2bfloat16(vv[j]);
        float hf = __bfloat162float(h);
        hi[i * 4 + j] = h;
        lo[i * 4 + j] = __float2bfloat16(vv[j] - hf);
    }
}

__global__ void split_transpose(const float* __restrict__ in,
                                __nv_bfloat16* __restrict__ hi,
                                __nv_bfloat16* __restrict__ lo, int K, int N)
{
    __shared__ float t[32][33];
    int x = blockIdx.x * 32 + threadIdx.x;
    int y = blockIdx.y * 32 + threadIdx.y;
#pragma unroll
    for (int j = 0; j < 32; j += 8)
        t[threadIdx.y + j][threadIdx.x] = in[(size_t)(y + j) * N + x];
    __syncthreads();
    int xo = blockIdx.y * 32 + threadIdx.x;
    int yo = blockIdx.x * 32 + threadIdx.y;
#pragma unroll
    for (int j = 0; j < 32; j += 8) {
        float v = t[threadIdx.x][threadIdx.y + j];
        __nv_bfloat16 h = __float2bfloat16(v);
        float hf = __bfloat162float(h);
        size_t idx = (size_t)(yo + j) * K + xo;
        hi[idx] = h;
        lo[idx] = __float2bfloat16(v - hf);
    }
}

// ---------------- mma.sync split-bf16 GEMM --------------------------------
// SPLIT=false: C fp32 = A@B^T + bias.   SPLIT=true: write bf16 hi/lo split.
template <int Mdim, int Ndim, int Kdim, bool SPLIT>
__global__ __launch_bounds__(256)
void gemm_mma(const __nv_bfloat16* __restrict__ Ahi,
              const __nv_bfloat16* __restrict__ Alo,
              const __nv_bfloat16* __restrict__ Bhi,
              const __nv_bfloat16* __restrict__ Blo,
              const float* __restrict__ bias, float* __restrict__ C,
              __nv_bfloat16* __restrict__ Chi, __nv_bfloat16* __restrict__ Clo)
{
    constexpr int NCHUNK = Kdim / 32;
    constexpr uint32_t STAGE = 40960;
    constexpr uint32_t MATB = 10240;

    extern __shared__ char smem[];
    const uint32_t sbase = smem_u32(smem);

    const int tid  = threadIdx.x;
    const int wid  = tid >> 5;
    const int lane = tid & 31;
    const int m0 = blockIdx.y * 128;
    const int n0 = blockIdx.x * 128;
    const int wm = (wid >> 2) * 64;
    const int wn = (wid & 3) * 32;

    const int arow = lane & 15;
    const int ak8  = (lane >> 4) * 8;
    const int bn   = ((lane >> 4) << 3) + (lane & 7);
    const int bk8  = lane & 8;

    auto load_chunk = [&](int c, int st) {
        const int k0 = c * 32;
        const uint32_t sb = sbase + (uint32_t)st * STAGE;
#pragma unroll
        for (int t = 0; t < 8; t++) {
            int i = tid + t * 256;
            int mat = i >> 9;
            int rem = i & 511;
            int row = rem >> 2, seg = rem & 3;
            uint32_t dst = sb + (uint32_t)mat * MATB + row * 80 + seg * 16;
            const __nv_bfloat16* src;
            if (mat == 0)      src = Ahi + (size_t)(m0 + row) * Kdim + k0 + seg * 8;
            else if (mat == 1) src = Alo + (size_t)(m0 + row) * Kdim + k0 + seg * 8;
            else if (mat == 2) src = Bhi + (size_t)(n0 + row) * Kdim + k0 + seg * 8;
            else               src = Blo + (size_t)(n0 + row) * Kdim + k0 + seg * 8;
            cp_async16(dst, src);
        }
    };

    float acc[4][4][4];
#pragma unroll
    for (int i = 0; i < 4; i++)
#pragma unroll
        for (int j = 0; j < 4; j++)
#pragma unroll
            for (int k = 0; k < 4; k++) acc[i][j][k] = 0.f;

    load_chunk(0, 0); CP_COMMIT();
    load_chunk(1, 1); CP_COMMIT();

    for (int c = 0; c < NCHUNK; c++) {
        CP_WAIT1();
        __syncthreads();
        if (c + 2 < NCHUNK) load_chunk(c + 2, (c + 2) % 3);
        CP_COMMIT();

        const uint32_t sb = sbase + (uint32_t)(c % 3) * STAGE;
        const uint32_t sAh = sb, sAl = sb + MATB, sBh = sb + 2 * MATB, sBl = sb + 3 * MATB;

        uint32_t ah[4][4], al[4][4], bh[4][2], bl[4][2];
#pragma unroll
        for (int ks = 0; ks < 2; ks++) {
            const uint32_t kb = ks * 32;
#pragma unroll
            for (int mf = 0; mf < 4; mf++) {
                uint32_t ra = (uint32_t)(wm + mf * 16 + arow) * 80 + kb + ak8 * 2;
                LDSM4(ah[mf][0], ah[mf][1], ah[mf][2], ah[mf][3], sAh + ra);
                LDSM4(al[mf][0], al[mf][1], al[mf][2], al[mf][3], sAl + ra);
            }
#pragma unroll
            for (int np = 0; np < 2; np++) {
                uint32_t rb = (uint32_t)(wn + np * 16 + bn) * 80 + kb + bk8 * 2;
                LDSM4(bh[np * 2][0], bh[np * 2][1], bh[np * 2 + 1][0], bh[np * 2 + 1][1],
                      sBh + rb);
                LDSM4(bl[np * 2][0], bl[np * 2][1], bl[np * 2 + 1][0], bl[np * 2 + 1][1],
                      sBl + rb);
            }
#pragma unroll
            for (int mf = 0; mf < 4; mf++)
#pragma unroll
                for (int nf = 0; nf < 4; nf++) {
                    MMA16816(acc[mf][nf], ah[mf], bh[nf]);
                    MMA16816(acc[mf][nf], ah[mf], bl[nf]);
                    MMA16816(acc[mf][nf], al[mf], bh[nf]);
                }
        }
    }

    const int r0 = lane >> 2;
    const int c0 = (lane & 3) * 2;
#pragma unroll
    for (int mf = 0; mf < 4; mf++) {
#pragma unroll
        for (int nf = 0; nf < 4; nf++) {
            int row = m0 + wm + mf * 16 + r0;
            int col = n0 + wn + nf * 8 + c0;
            float2 b2 = *(const float2*)(bias + col);
            float y00 = acc[mf][nf][0] + b2.x;
            float y01 = acc[mf][nf][1] + b2.y;
            float y10 = acc[mf][nf][2] + b2.x;
            float y11 = acc[mf][nf][3] + b2.y;
            if (!SPLIT) {
                *(float2*)(C + (size_t)row * Ndim + col) = make_float2(y00, y01);
                *(float2*)(C + (size_t)(row + 8) * Ndim + col) = make_float2(y10, y11);
            } else {
                *(uint32_t*)(Chi + (size_t)row * Ndim + col) = packhi2(y00, y01);
                *(uint32_t*)(Clo + (size_t)row * Ndim + col) =
                    packbf2(y01 - truncbf(y01), y00 - truncbf(y00));
                *(uint32_t*)(Chi + (size_t)(row + 8) * Ndim + col) = packhi2(y10, y11);
                *(uint32_t*)(Clo + (size_t)(row + 8) * Ndim + col) =
                    packbf2(y11 - truncbf(y11), y10 - truncbf(y10));
            }
        }
    }
}

// ---------------- flash attention on mma.sync (split bf16) -----------------
// CTA: one (b, h, 64-row Q tile). 128 threads, 4 warps, each warp 16 Q rows.
// KV tiles of 64, 2-stage cp.async pipeline. S and PV both split-3.
__global__ __launch_bounds__(128)
void flash_mma(const __nv_bfloat16* __restrict__ qh_,
               const __nv_bfloat16* __restrict__ ql_,
               __nv_bfloat16* __restrict__ yhi,
               __nv_bfloat16* __restrict__ ylo)
{
    constexpr uint32_t RSTR = 144;      // padded row stride (bytes): 64 bf16 + pad
    constexpr uint32_t TB   = 9216;     // one 64-row tile: 64*144
    constexpr uint32_t QH = 0, QL = TB;
    constexpr uint32_t K0 = 2 * TB;     // K stage base
    constexpr uint32_t V0 = 6 * TB;     // V stage base
    constexpr uint32_t KVSTG = 2 * TB;  // per-stage (hi+lo)

    extern __shared__ char smem[];
    const uint32_t sbase = smem_u32(smem);

    const int tid  = threadIdx.x;
    const int wid  = tid >> 5;
    const int lane = tid & 31;
    const int qt   = (Tt / 64 - 1) - blockIdx.x;  // long CTAs first
    const int bh   = blockIdx.y;
    const int b    = bh >> 4;
    const int h    = bh & 15;
    const int wm   = wid * 16;

    const size_t rs = 3 * Cc;
    const size_t rowbase = (size_t)b * Tt;

    auto loadKV = [&](int kt, int st) {
        const uint32_t kb = sbase + K0 + (uint32_t)st * KVSTG;
        const uint32_t vb = sbase + V0 + (uint32_t)st * KVSTG;
#pragma unroll
        for (int i = tid; i < 512; i += 128) {
            int r = i >> 3, s = i & 7;
            uint32_t off = (uint32_t)r * RSTR + s * 16;
            size_t gk = (rowbase + kt * 64 + r) * rs + Cc + h * HDm + s * 8;
            size_t gv = gk + Cc;
            cp_async16(kb + off, qh_ + gk);
            cp_async16(kb + TB + off, ql_ + gk);
            cp_async16(vb + off, qh_ + gv);
            cp_async16(vb + TB + off, ql_ + gv);
        }
    };

    // ---- preload Q + KV0, KV1 ----
    {
#pragma unroll
        for (int i = tid; i < 512; i += 128) {
            int r = i >> 3, s = i & 7;
            uint32_t off = (uint32_t)r * RSTR + s * 16;
            size_t gq = (rowbase + qt * 64 + r) * rs + h * HDm + s * 8;
            cp_async16(sbase + QH + off, qh_ + gq);
            cp_async16(sbase + QL + off, ql_ + gq);
        }
        loadKV(0, 0);
    }
    CP_COMMIT();
    if (qt > 0) loadKV(1, 1);
    CP_COMMIT();

    CP_WAIT1();
    __syncthreads();

    // ---- Q fragments (held in regs for whole loop) ----
    uint32_t qfh[4][4], qfl[4][4];
    {
        const int arow = lane & 15;
        const int ak16 = (lane >> 4) * 16;
#pragma unroll
        for (int ks = 0; ks < 4; ks++) {
            uint32_t ra = (uint32_t)(wm + arow) * RSTR + ks * 32 + ak16;
            LDSM4(qfh[ks][0], qfh[ks][1], qfh[ks][2], qfh[ks][3], sbase + QH + ra);
            LDSM4(qfl[ks][0], qfl[ks][1], qfl[ks][2], qfl[ks][3], sbase + QL + ra);
        }
    }

    float o[8][4];
#pragma unroll
    for (int i = 0; i < 8; i++)
#pragma unroll
        for (int j = 0; j < 4; j++) o[i][j] = 0.f;
    float m0v = -1e30f, m1v = -1e30f, l0 = 0.f, l1 = 0.f;

    const int gid = lane >> 2;
    const int tig = lane & 3;

    for (int kt = 0; kt <= qt; kt++) {
        if (kt) { CP_WAIT1(); __syncthreads(); }
        const int st = kt & 1;
        const uint32_t sk = sbase + K0 + (uint32_t)st * KVSTG;
        const uint32_t sv = sbase + V0 + (uint32_t)st * KVSTG;

        // ---- S = Q K^T (split-3) ----
        float s[8][4];
#pragma unroll
        for (int i = 0; i < 8; i++)
#pragma unroll
            for (int j = 0; j < 4; j++) s[i][j] = 0.f;

        const int brow = ((lane >> 4) << 3) + (lane & 7);
        const int bk16 = (lane & 8) * 2;
#pragma unroll
        for (int ks = 0; ks < 4; ks++) {
            const uint32_t kb = ks * 32;
#pragma unroll
            for (int np = 0; np < 4; np++) {
                uint32_t ro = (uint32_t)(np * 16 + brow) * RSTR + kb + bk16;
                uint32_t b0, b1, b2, b3, c0, c1, c2, c3;
                LDSM4(b0, b1, b2, b3, sk + ro);
                LDSM4(c0, c1, c2, c3, sk + TB + ro);
                MMA2(s[2 * np], qfh[ks], b0, b1);
                MMA2(s[2 * np], qfh[ks], c0, c1);
                MMA2(s[2 * np], qfl[ks], b0, b1);
                MMA2(s[2 * np + 1], qfh[ks], b2, b3);
                MMA2(s[2 * np + 1], qfh[ks], c2, c3);
                MMA2(s[2 * np + 1], qfl[ks], b2, b3);
            }
        }

        // ---- scale + causal mask ----
#pragma unroll
        for (int i = 0; i < 8; i++)
#pragma unroll
            for (int j = 0; j < 4; j++) s[i][j] *= 0.125f;

        if (kt == qt) {
            const int rr0 = wm + gid, rr1 = wm + gid + 8;
#pragma unroll
            for (int nf = 0; nf < 8; nf++) {
                int cc0 = nf * 8 + tig * 2;
                if (cc0 > rr0) s[nf][0] = -1e30f;
                if (cc0 + 1 > rr0) s[nf][1] = -1e30f;
                if (cc0 > rr1) s[nf][2] = -1e30f;
                if (cc0 + 1 > rr1) s[nf][3] = -1e30f;
            }
        }

        // ---- online softmax (two row-sets per thread) ----
        float mx0 = -1e30f, mx1 = -1e30f;
#pragma unroll
        for (int nf = 0; nf < 8; nf++) {
            mx0 = fmaxf(mx0, fmaxf(s[nf][0], s[nf][1]));
            mx1 = fmaxf(mx1, fmaxf(s[nf][2], s[nf][3]));
        }
        mx0 = fmaxf(mx0, __shfl_xor_sync(0xffffffffu, mx0, 1));
        mx0 = fmaxf(mx0, __shfl_xor_sync(0xffffffffu, mx0, 2));
        mx1 = fmaxf(mx1, __shfl_xor_sync(0xffffffffu, mx1, 1));
        mx1 = fmaxf(mx1, __shfl_xor_sync(0xffffffffu, mx1, 2));

        float mn0 = fmaxf(m0v, mx0), mn1 = fmaxf(m1v, mx1);
        float fac0 = __expf(m0v - mn0), fac1 = __expf(m1v - mn1);
        float sum0 = 0.f, sum1 = 0.f;
#pragma unroll
        for (int nf = 0; nf < 8; nf++) {
            s[nf][0] = __expf(s[nf][0] - mn0); sum0 += s[nf][0];
            s[nf][1] = __expf(s[nf][1] - mn0); sum0 += s[nf][1];
            s[nf][2] = __expf(s[nf][2] - mn1); sum1 += s[nf][2];
            s[nf][3] = __expf(s[nf][3] - mn1); sum1 += s[nf][3];
        }
        sum0 += __shfl_xor_sync(0xffffffffu, sum0, 1);
        sum0 += __shfl_xor_sync(0xffffffffu, sum0, 2);
        sum1 += __shfl_xor_sync(0xffffffffu, sum1, 1);
        sum1 += __shfl_xor_sync(0xffffffffu, sum1, 2);
        l0 = l0 * fac0 + sum0; m0v = mn0;
        l1 = l1 * fac1 + sum1; m1v = mn1;
#pragma unroll
        for (int nh = 0; nh < 8; nh++) {
            o[nh][0] *= fac0; o[nh][1] *= fac0;
            o[nh][2] *= fac1; o[nh][3] *= fac1;
        }

        // ---- O += P V (split-3), P built in-register ----
        const int vrow = lane & 15;
        const int vcol16 = (lane >> 4) * 16;
#pragma unroll
        for (int ks = 0; ks < 4; ks++) {
            uint32_t ah[4], al[4];
            {
                float p00 = s[2 * ks][0], p01 = s[2 * ks][1];
                float p10 = s[2 * ks][2], p11 = s[2 * ks][3];
                float p20 = s[2 * ks + 1][0], p21 = s[2 * ks + 1][1];
                float p30 = s[2 * ks + 1][2], p31 = s[2 * ks + 1][3];
                ah[0] = packhi2(p00, p01);
                ah[1] = packhi2(p10, p11);
                ah[2] = packhi2(p20, p21);
                ah[3] = packhi2(p30, p31);
                al[0] = packbf2(p01 - truncbf(p01), p00 - truncbf(p00));
                al[1] = packbf2(p11 - truncbf(p11), p10 - truncbf(p10));
                al[2] = packbf2(p21 - truncbf(p21), p20 - truncbf(p20));
                al[3] = packbf2(p31 - truncbf(p31), p30 - truncbf(p30));
            }
#pragma unroll
            for (int np = 0; np < 4; np++) {
                uint32_t vo = (uint32_t)(ks * 16 + vrow) * RSTR + np * 32 + vcol16;
                uint32_t v0, v1, v2, v3, w0, w1, w2, w3;
                LDSM4T(v0, v1, v2, v3, sv + vo);
                LDSM4T(w0, w1, w2, w3, sv + TB + vo);
                MMA2(o[2 * np], ah, v0, v1);
                MMA2(o[2 * np], ah, w0, w1);
                MMA2(o[2 * np], al, v0, v1);
                MMA2(o[2 * np + 1], ah, v2, v3);
                MMA2(o[2 * np + 1], ah, w2, w3);
                MMA2(o[2 * np + 1], al, v2, v3);
            }
        }

        __syncthreads();
        if (kt + 2 <= qt) loadKV(kt + 2, st);
        CP_COMMIT();
    }

    // ---- epilogue: write y split bf16 ----
    float inv0 = 1.0f / l0, inv1 = 1.0f / l1;
    const size_t row0 = rowbase + qt * 64 + wm + gid;
    const int colb = h * HDm + tig * 2;
#pragma unroll
    for (int nh = 0; nh < 8; nh++) {
        int col = colb + nh * 8;
        float y00 = o[nh][0] * inv0, y01 = o[nh][1] * inv0;
        float y10 = o[nh][2] * inv1, y11 = o[nh][3] * inv1;
        *(uint32_t*)(yhi + row0 * Cc + col) = packhi2(y00, y01);
        *(uint32_t*)(ylo + row0 * Cc + col) =
            packbf2(y01 - truncbf(y01), y00 - truncbf(y00));
        *(uint32_t*)(yhi + (row0 + 8) * Cc + col) = packhi2(y10, y11);
        *(uint32_t*)(ylo + (row0 + 8) * Cc + col) =
            packbf2(y11 - truncbf(y11), y10 - truncbf(y10));
    }
}

// ---------------- launch ---------------------------------------------------
extern "C" void kernel_launch(void* const* d_in, const int* in_sizes, int n_in,
                              void* d_out, int out_size)
{
    const float* x      = (const float*)d_in[0];
    const float* w_attn = (const float*)d_in[1];
    const float* b_attn = (const float*)d_in[2];
    const float* w_proj = (const float*)d_in[3];
    const float* b_proj = (const float*)d_in[4];
    float* out = (float*)d_out;

    __nv_bfloat16 *qkvhi, *qkvlo, *xhi, *xlo, *yhi, *ylo, *wahi, *walo, *wphi, *wplo;
    cudaGetSymbolAddress((void**)&qkvhi, g_qkvhi);
    cudaGetSymbolAddress((void**)&qkvlo, g_qkvlo);
    cudaGetSymbolAddress((void**)&xhi, g_xhi);
    cudaGetSymbolAddress((void**)&xlo, g_xlo);
    cudaGetSymbolAddress((void**)&yhi, g_yhi);
    cudaGetSymbolAddress((void**)&ylo, g_ylo);
    cudaGetSymbolAddress((void**)&wahi, g_wahi);
    cudaGetSymbolAddress((void**)&walo, g_walo);
    cudaGetSymbolAddress((void**)&wphi, g_wphi);
    cudaGetSymbolAddress((void**)&wplo, g_wplo);

    constexpr int GEMM_SMEM = 3 * 40960;
    cudaFuncSetAttribute(gemm_mma<Bb * Tt, 3 * Cc, Cc, true>,
                         cudaFuncAttributeMaxDynamicSharedMemorySize, GEMM_SMEM);
    cudaFuncSetAttribute(gemm_mma<Bb * Tt, Cc, Cc, false>,
                         cudaFuncAttributeMaxDynamicSharedMemorySize, GEMM_SMEM);
    constexpr int FLASH_SMEM = 10 * 9216;  // 92160
    cudaFuncSetAttribute(flash_mma, cudaFuncAttributeMaxDynamicSharedMemorySize,
                         FLASH_SMEM);

    // 1) split input x and weights into bf16 hi/lo
    {
        int n4 = (Bb * Tt * Cc) / 4;
        split_rows<<<(n4 + 255) / 256, 256>>>((const float4*)x, xhi, xlo, n4);
        split_transpose<<<dim3((3 * Cc) / 32, Cc / 32), dim3(32, 8)>>>(
            w_attn, wahi, walo, Cc, 3 * Cc);
        split_transpose<<<dim3(Cc / 32, Cc / 32), dim3(32, 8)>>>(
            w_proj, wphi, wplo, Cc, Cc);
    }

    // 2) QKV GEMM -> split bf16 qkv directly
    gemm_mma<Bb * Tt, 3 * Cc, Cc, true>
        <<<dim3((3 * Cc) / 128, (Bb * Tt) / 128), 256, GEMM_SMEM>>>(
            xhi, xlo, wahi, walo, b_attn, nullptr, qkvhi, qkvlo);

    // 3) causal flash attention on tensor cores -> split bf16 y
    flash_mma<<<dim3(Tt / 64, Bb * Hh), 128, FLASH_SMEM>>>(qkvhi, qkvlo, yhi, ylo);

    // 4) output projection -> fp32 out
    gemm_mma<Bb * Tt, Cc, Cc, false>
        <<<dim3(Cc / 128, (Bb * Tt) / 128), 256, GEMM_SMEM>>>(
            yhi, ylo, wphi, wplo, b_proj, out, nullptr, nullptr);
}

// round 5
// speedup vs baseline: 3.3958x; 1.1125x over previous
#include <cuda_runtime.h>
#include <cuda_bf16.h>
#include <cstdint>

#define Bb 4
#define Tt 2048
#define Cc 1024
#define Hh 16
#define HDm 64

// ---------------- scratch ------------------------------------------------
__device__ __nv_bfloat16 g_qkvhi[(size_t)Bb * Tt * 3 * Cc];  // [8192, 3072]
__device__ __nv_bfloat16 g_qkvlo[(size_t)Bb * Tt * 3 * Cc];
__device__ __nv_bfloat16 g_xhi[(size_t)Bb * Tt * Cc];
__device__ __nv_bfloat16 g_xlo[(size_t)Bb * Tt * Cc];
__device__ __nv_bfloat16 g_yhi[(size_t)Bb * Tt * Cc];
__device__ __nv_bfloat16 g_ylo[(size_t)Bb * Tt * Cc];
__device__ __nv_bfloat16 g_wahi[(size_t)3 * Cc * Cc];        // [3072,1024] (N,K)
__device__ __nv_bfloat16 g_walo[(size_t)3 * Cc * Cc];
__device__ __nv_bfloat16 g_wphi[(size_t)Cc * Cc];
__device__ __nv_bfloat16 g_wplo[(size_t)Cc * Cc];

// ---------------- helpers ------------------------------------------------
__device__ __forceinline__ uint32_t smem_u32(const void* p) {
    return (uint32_t)__cvta_generic_to_shared(p);
}
__device__ __forceinline__ void cp_async16(uint32_t dst, const void* src) {
    asm volatile("cp.async.cg.shared.global [%0], [%1], 16;\n"
                 :: "r"(dst), "l"(src));
}
#define CP_COMMIT() asm volatile("cp.async.commit_group;\n" ::: "memory")
#define CP_WAIT1()  asm volatile("cp.async.wait_group 1;\n" ::: "memory")
#define CP_WAIT0()  asm volatile("cp.async.wait_group 0;\n" ::: "memory")

#define LDSM4(r0, r1, r2, r3, addr) \
    asm volatile("ldmatrix.sync.aligned.m8n8.x4.shared.b16 {%0,%1,%2,%3}, [%4];" \
                 : "=r"(r0), "=r"(r1), "=r"(r2), "=r"(r3) : "r"(addr))
#define LDSM4T(r0, r1, r2, r3, addr) \
    asm volatile("ldmatrix.sync.aligned.m8n8.x4.trans.shared.b16 {%0,%1,%2,%3}, [%4];" \
                 : "=r"(r0), "=r"(r1), "=r"(r2), "=r"(r3) : "r"(addr))

#define MMA16816(d, a, b) \
    asm volatile("mma.sync.aligned.m16n8k16.row.col.f32.bf16.bf16.f32 " \
                 "{%0,%1,%2,%3}, {%4,%5,%6,%7}, {%8,%9}, {%0,%1,%2,%3};" \
                 : "+f"((d)[0]), "+f"((d)[1]), "+f"((d)[2]), "+f"((d)[3]) \
                 : "r"((a)[0]), "r"((a)[1]), "r"((a)[2]), "r"((a)[3]), \
                   "r"((b)[0]), "r"((b)[1]))
#define MMA2(d, a, bv0, bv1) \
    asm volatile("mma.sync.aligned.m16n8k16.row.col.f32.bf16.bf16.f32 " \
                 "{%0,%1,%2,%3}, {%4,%5,%6,%7}, {%8,%9}, {%0,%1,%2,%3};" \
                 : "+f"((d)[0]), "+f"((d)[1]), "+f"((d)[2]), "+f"((d)[3]) \
                 : "r"((a)[0]), "r"((a)[1]), "r"((a)[2]), "r"((a)[3]), \
                   "r"(bv0), "r"(bv1))

__device__ __forceinline__ uint32_t packbf2(float hi, float lo) {
    uint32_t d;
    asm("cvt.rn.bf16x2.f32 %0, %1, %2;" : "=r"(d) : "f"(hi), "f"(lo));
    return d;
}
__device__ __forceinline__ float truncbf(float x) {
    return __uint_as_float(__float_as_uint(x) & 0xffff0000u);
}
__device__ __forceinline__ uint32_t packhi2(float p0, float p1) {
    return __byte_perm(__float_as_uint(p0), __float_as_uint(p1), 0x7632);
}

// ---------------- conversion kernels --------------------------------------
__global__ void split_rows(const float4* __restrict__ in,
                           __nv_bfloat16* __restrict__ hi,
                           __nv_bfloat16* __restrict__ lo, int n4)
{
    int i = blockIdx.x * blockDim.x + threadIdx.x;
    if (i >= n4) return;
    float4 v = in[i];
    float vv[4] = {v.x, v.y, v.z, v.w};
#pragma unroll
    for (int j = 0; j < 4; j++) {
        __nv_bfloat16 h = __float2bfloat16(vv[j]);
        float hf = __bfloat162float(h);
        hi[i * 4 + j] = h;
        lo[i * 4 + j] = __float2bfloat16(vv[j] - hf);
    }
}

__global__ void split_transpose(const float* __restrict__ in,
                                __nv_bfloat16* __restrict__ hi,
                                __nv_bfloat16* __restrict__ lo, int K, int N)
{
    __shared__ float t[32][33];
    int x = blockIdx.x * 32 + threadIdx.x;
    int y = blockIdx.y * 32 + threadIdx.y;
#pragma unroll
    for (int j = 0; j < 32; j += 8)
        t[threadIdx.y + j][threadIdx.x] = in[(size_t)(y + j) * N + x];
    __syncthreads();
    int xo = blockIdx.y * 32 + threadIdx.x;
    int yo = blockIdx.x * 32 + threadIdx.y;
#pragma unroll
    for (int j = 0; j < 32; j += 8) {
        float v = t[threadIdx.x][threadIdx.y + j];
        __nv_bfloat16 h = __float2bfloat16(v);
        float hf = __bfloat162float(h);
        size_t idx = (size_t)(yo + j) * K + xo;
        hi[idx] = h;
        lo[idx] = __float2bfloat16(v - hf);
    }
}

// ---------------- mma.sync split-bf16 GEMM --------------------------------
// 2-stage pipeline, 2 CTAs/SM. SPLIT selects fp32 vs bf16 hi/lo output.
template <int Mdim, int Ndim, int Kdim, bool SPLIT>
__global__ __launch_bounds__(256, 2)
void gemm_mma(const __nv_bfloat16* __restrict__ Ahi,
              const __nv_bfloat16* __restrict__ Alo,
              const __nv_bfloat16* __restrict__ Bhi,
              const __nv_bfloat16* __restrict__ Blo,
              const float* __restrict__ bias, float* __restrict__ C,
              __nv_bfloat16* __restrict__ Chi, __nv_bfloat16* __restrict__ Clo)
{
    constexpr int NCHUNK = Kdim / 32;
    constexpr uint32_t STAGE = 40960;
    constexpr uint32_t MATB = 10240;

    extern __shared__ char smem[];
    const uint32_t sbase = smem_u32(smem);

    const int tid  = threadIdx.x;
    const int wid  = tid >> 5;
    const int lane = tid & 31;
    const int m0 = blockIdx.y * 128;
    const int n0 = blockIdx.x * 128;
    const int wm = (wid >> 2) * 64;
    const int wn = (wid & 3) * 32;

    const int arow = lane & 15;
    const int ak8  = (lane >> 4) * 8;
    const int bn   = ((lane >> 4) << 3) + (lane & 7);
    const int bk8  = lane & 8;

    auto load_chunk = [&](int c, int st) {
        const int k0 = c * 32;
        const uint32_t sb = sbase + (uint32_t)st * STAGE;
#pragma unroll
        for (int t = 0; t < 8; t++) {
            int i = tid + t * 256;
            int mat = i >> 9;
            int rem = i & 511;
            int row = rem >> 2, seg = rem & 3;
            uint32_t dst = sb + (uint32_t)mat * MATB + row * 80 + seg * 16;
            const __nv_bfloat16* src;
            if (mat == 0)      src = Ahi + (size_t)(m0 + row) * Kdim + k0 + seg * 8;
            else if (mat == 1) src = Alo + (size_t)(m0 + row) * Kdim + k0 + seg * 8;
            else if (mat == 2) src = Bhi + (size_t)(n0 + row) * Kdim + k0 + seg * 8;
            else               src = Blo + (size_t)(n0 + row) * Kdim + k0 + seg * 8;
            cp_async16(dst, src);
        }
    };

    float acc[4][4][4];
#pragma unroll
    for (int i = 0; i < 4; i++)
#pragma unroll
        for (int j = 0; j < 4; j++)
#pragma unroll
            for (int k = 0; k < 4; k++) acc[i][j][k] = 0.f;

    load_chunk(0, 0); CP_COMMIT();

    for (int c = 0; c < NCHUNK; c++) {
        CP_WAIT0();        // chunk c resident
        __syncthreads();   // all warps done with compute(c-1) -> buffer (c+1)&1 free
        if (c + 1 < NCHUNK) { load_chunk(c + 1, (c + 1) & 1); CP_COMMIT(); }

        const uint32_t sb = sbase + (uint32_t)(c & 1) * STAGE;
        const uint32_t sAh = sb, sAl = sb + MATB, sBh = sb + 2 * MATB, sBl = sb + 3 * MATB;

        uint32_t ah[4][4], al[4][4], bh[4][2], bl[4][2];
#pragma unroll
        for (int ks = 0; ks < 2; ks++) {
            const uint32_t kb = ks * 32;
#pragma unroll
            for (int mf = 0; mf < 4; mf++) {
                uint32_t ra = (uint32_t)(wm + mf * 16 + arow) * 80 + kb + ak8 * 2;
                LDSM4(ah[mf][0], ah[mf][1], ah[mf][2], ah[mf][3], sAh + ra);
                LDSM4(al[mf][0], al[mf][1], al[mf][2], al[mf][3], sAl + ra);
            }
#pragma unroll
            for (int np = 0; np < 2; np++) {
                uint32_t rb = (uint32_t)(wn + np * 16 + bn) * 80 + kb + bk8 * 2;
                LDSM4(bh[np * 2][0], bh[np * 2][1], bh[np * 2 + 1][0], bh[np * 2 + 1][1],
                      sBh + rb);
                LDSM4(bl[np * 2][0], bl[np * 2][1], bl[np * 2 + 1][0], bl[np * 2 + 1][1],
                      sBl + rb);
            }
#pragma unroll
            for (int mf = 0; mf < 4; mf++)
#pragma unroll
                for (int nf = 0; nf < 4; nf++) {
                    MMA16816(acc[mf][nf], ah[mf], bh[nf]);
                    MMA16816(acc[mf][nf], ah[mf], bl[nf]);
                    MMA16816(acc[mf][nf], al[mf], bh[nf]);
                }
        }
    }

    const int r0 = lane >> 2;
    const int c0 = (lane & 3) * 2;
#pragma unroll
    for (int mf = 0; mf < 4; mf++) {
#pragma unroll
        for (int nf = 0; nf < 4; nf++) {
            int row = m0 + wm + mf * 16 + r0;
            int col = n0 + wn + nf * 8 + c0;
            float2 b2 = *(const float2*)(bias + col);
            float y00 = acc[mf][nf][0] + b2.x;
            float y01 = acc[mf][nf][1] + b2.y;
            float y10 = acc[mf][nf][2] + b2.x;
            float y11 = acc[mf][nf][3] + b2.y;
            if (!SPLIT) {
                *(float2*)(C + (size_t)row * Ndim + col) = make_float2(y00, y01);
                *(float2*)(C + (size_t)(row + 8) * Ndim + col) = make_float2(y10, y11);
            } else {
                *(uint32_t*)(Chi + (size_t)row * Ndim + col) = packhi2(y00, y01);
                *(uint32_t*)(Clo + (size_t)row * Ndim + col) =
                    packbf2(y01 - truncbf(y01), y00 - truncbf(y00));
                *(uint32_t*)(Chi + (size_t)(row + 8) * Ndim + col) = packhi2(y10, y11);
                *(uint32_t*)(Clo + (size_t)(row + 8) * Ndim + col) =
                    packbf2(y11 - truncbf(y11), y10 - truncbf(y10));
            }
        }
    }
}

// ---------------- flash attention on mma.sync (split bf16) -----------------
__global__ __launch_bounds__(128)
void flash_mma(const __nv_bfloat16* __restrict__ qh_,
               const __nv_bfloat16* __restrict__ ql_,
               __nv_bfloat16* __restrict__ yhi,
               __nv_bfloat16* __restrict__ ylo)
{
    constexpr uint32_t RSTR = 144;
    constexpr uint32_t TB   = 9216;
    constexpr uint32_t QH = 0, QL = TB;
    constexpr uint32_t K0 = 2 * TB;
    constexpr uint32_t V0 = 6 * TB;
    constexpr uint32_t KVSTG = 2 * TB;

    extern __shared__ char smem[];
    const uint32_t sbase = smem_u32(smem);

    const int tid  = threadIdx.x;
    const int wid  = tid >> 5;
    const int lane = tid & 31;
    const int qt   = (Tt / 64 - 1) - blockIdx.x;
    const int bh   = blockIdx.y;
    const int b    = bh >> 4;
    const int h    = bh & 15;
    const int wm   = wid * 16;

    const size_t rs = 3 * Cc;
    const size_t rowbase = (size_t)b * Tt;

    auto loadKV = [&](int kt, int st) {
        const uint32_t kb = sbase + K0 + (uint32_t)st * KVSTG;
        const uint32_t vb = sbase + V0 + (uint32_t)st * KVSTG;
#pragma unroll
        for (int i = tid; i < 512; i += 128) {
            int r = i >> 3, s = i & 7;
            uint32_t off = (uint32_t)r * RSTR + s * 16;
            size_t gk = (rowbase + kt * 64 + r) * rs + Cc + h * HDm + s * 8;
            size_t gv = gk + Cc;
            cp_async16(kb + off, qh_ + gk);
            cp_async16(kb + TB + off, ql_ + gk);
            cp_async16(vb + off, qh_ + gv);
            cp_async16(vb + TB + off, ql_ + gv);
        }
    };

    {
#pragma unroll
        for (int i = tid; i < 512; i += 128) {
            int r = i >> 3, s = i & 7;
            uint32_t off = (uint32_t)r * RSTR + s * 16;
            size_t gq = (rowbase + qt * 64 + r) * rs + h * HDm + s * 8;
            cp_async16(sbase + QH + off, qh_ + gq);
            cp_async16(sbase + QL + off, ql_ + gq);
        }
        loadKV(0, 0);
    }
    CP_COMMIT();
    if (qt > 0) loadKV(1, 1);
    CP_COMMIT();

    CP_WAIT1();
    __syncthreads();

    uint32_t qfh[4][4], qfl[4][4];
    {
        const int arow = lane & 15;
        const int ak16 = (lane >> 4) * 16;
#pragma unroll
        for (int ks = 0; ks < 4; ks++) {
            uint32_t ra = (uint32_t)(wm + arow) * RSTR + ks * 32 + ak16;
            LDSM4(qfh[ks][0], qfh[ks][1], qfh[ks][2], qfh[ks][3], sbase + QH + ra);
            LDSM4(qfl[ks][0], qfl[ks][1], qfl[ks][2], qfl[ks][3], sbase + QL + ra);
        }
    }

    float o[8][4];
#pragma unroll
    for (int i = 0; i < 8; i++)
#pragma unroll
        for (int j = 0; j < 4; j++) o[i][j] = 0.f;
    float m0v = -1e30f, m1v = -1e30f, l0 = 0.f, l1 = 0.f;

    const int gid = lane >> 2;
    const int tig = lane & 3;

    for (int kt = 0; kt <= qt; kt++) {
        if (kt) { CP_WAIT1(); __syncthreads(); }
        const int st = kt & 1;
        const uint32_t sk = sbase + K0 + (uint32_t)st * KVSTG;
        const uint32_t sv = sbase + V0 + (uint32_t)st * KVSTG;

        float s[8][4];
#pragma unroll
        for (int i = 0; i < 8; i++)
#pragma unroll
            for (int j = 0; j < 4; j++) s[i][j] = 0.f;

        const int brow = ((lane >> 4) << 3) + (lane & 7);
        const int bk16 = (lane & 8) * 2;
#pragma unroll
        for (int ks = 0; ks < 4; ks++) {
            const uint32_t kb = ks * 32;
#pragma unroll
            for (int np = 0; np < 4; np++) {
                uint32_t ro = (uint32_t)(np * 16 + brow) * RSTR + kb + bk16;
                uint32_t b0, b1, b2, b3, c0, c1, c2, c3;
                LDSM4(b0, b1, b2, b3, sk + ro);
                LDSM4(c0, c1, c2, c3, sk + TB + ro);
                MMA2(s[2 * np], qfh[ks], b0, b1);
                MMA2(s[2 * np], qfh[ks], c0, c1);
                MMA2(s[2 * np], qfl[ks], b0, b1);
                MMA2(s[2 * np + 1], qfh[ks], b2, b3);
                MMA2(s[2 * np + 1], qfh[ks], c2, c3);
                MMA2(s[2 * np + 1], qfl[ks], b2, b3);
            }
        }

#pragma unroll
        for (int i = 0; i < 8; i++)
#pragma unroll
            for (int j = 0; j < 4; j++) s[i][j] *= 0.125f;

        if (kt == qt) {
            const int rr0 = wm + gid, rr1 = wm + gid + 8;
#pragma unroll
            for (int nf = 0; nf < 8; nf++) {
                int cc0 = nf * 8 + tig * 2;
                if (cc0 > rr0) s[nf][0] = -1e30f;
                if (cc0 + 1 > rr0) s[nf][1] = -1e30f;
                if (cc0 > rr1) s[nf][2] = -1e30f;
                if (cc0 + 1 > rr1) s[nf][3] = -1e30f;
            }
        }

        float mx0 = -1e30f, mx1 = -1e30f;
#pragma unroll
        for (int nf = 0; nf < 8; nf++) {
            mx0 = fmaxf(mx0, fmaxf(s[nf][0], s[nf][1]));
            mx1 = fmaxf(mx1, fmaxf(s[nf][2], s[nf][3]));
        }
        mx0 = fmaxf(mx0, __shfl_xor_sync(0xffffffffu, mx0, 1));
        mx0 = fmaxf(mx0, __shfl_xor_sync(0xffffffffu, mx0, 2));
        mx1 = fmaxf(mx1, __shfl_xor_sync(0xffffffffu, mx1, 1));
        mx1 = fmaxf(mx1, __shfl_xor_sync(0xffffffffu, mx1, 2));

        float mn0 = fmaxf(m0v, mx0), mn1 = fmaxf(m1v, mx1);
        float fac0 = __expf(m0v - mn0), fac1 = __expf(m1v - mn1);
        float sum0 = 0.f, sum1 = 0.f;
#pragma unroll
        for (int nf = 0; nf < 8; nf++) {
            s[nf][0] = __expf(s[nf][0] - mn0); sum0 += s[nf][0];
            s[nf][1] = __expf(s[nf][1] - mn0); sum0 += s[nf][1];
            s[nf][2] = __expf(s[nf][2] - mn1); sum1 += s[nf][2];
            s[nf][3] = __expf(s[nf][3] - mn1); sum1 += s[nf][3];
        }
        sum0 += __shfl_xor_sync(0xffffffffu, sum0, 1);
        sum0 += __shfl_xor_sync(0xffffffffu, sum0, 2);
        sum1 += __shfl_xor_sync(0xffffffffu, sum1, 1);
        sum1 += __shfl_xor_sync(0xffffffffu, sum1, 2);
        l0 = l0 * fac0 + sum0; m0v = mn0;
        l1 = l1 * fac1 + sum1; m1v = mn1;
#pragma unroll
        for (int nh = 0; nh < 8; nh++) {
            o[nh][0] *= fac0; o[nh][1] *= fac0;
            o[nh][2] *= fac1; o[nh][3] *= fac1;
        }

        const int vrow = lane & 15;
        const int vcol16 = (lane >> 4) * 16;
#pragma unroll
        for (int ks = 0; ks < 4; ks++) {
            uint32_t ah[4], al[4];
            {
                float p00 = s[2 * ks][0], p01 = s[2 * ks][1];
                float p10 = s[2 * ks][2], p11 = s[2 * ks][3];
                float p20 = s[2 * ks + 1][0], p21 = s[2 * ks + 1][1];
                float p30 = s[2 * ks + 1][2], p31 = s[2 * ks + 1][3];
                ah[0] = packhi2(p00, p01);
                ah[1] = packhi2(p10, p11);
                ah[2] = packhi2(p20, p21);
                ah[3] = packhi2(p30, p31);
                al[0] = packbf2(p01 - truncbf(p01), p00 - truncbf(p00));
                al[1] = packbf2(p11 - truncbf(p11), p10 - truncbf(p10));
                al[2] = packbf2(p21 - truncbf(p21), p20 - truncbf(p20));
                al[3] = packbf2(p31 - truncbf(p31), p30 - truncbf(p30));
            }
#pragma unroll
            for (int np = 0; np < 4; np++) {
                uint32_t vo = (uint32_t)(ks * 16 + vrow) * RSTR + np * 32 + vcol16;
                uint32_t v0, v1, v2, v3, w0, w1, w2, w3;
                LDSM4T(v0, v1, v2, v3, sv + vo);
                LDSM4T(w0, w1, w2, w3, sv + TB + vo);
                MMA2(o[2 * np], ah, v0, v1);
                MMA2(o[2 * np], ah, w0, w1);
                MMA2(o[2 * np], al, v0, v1);
                MMA2(o[2 * np + 1], ah, v2, v3);
                MMA2(o[2 * np + 1], ah, w2, w3);
                MMA2(o[2 * np + 1], al, v2, v3);
            }
        }

        __syncthreads();
        if (kt + 2 <= qt) loadKV(kt + 2, st);
        CP_COMMIT();
    }

    float inv0 = 1.0f / l0, inv1 = 1.0f / l1;
    const size_t row0 = rowbase + qt * 64 + wm + gid;
    const int colb = h * HDm + tig * 2;
#pragma unroll
    for (int nh = 0; nh < 8; nh++) {
        int col = colb + nh * 8;
        float y00 = o[nh][0] * inv0, y01 = o[nh][1] * inv0;
        float y10 = o[nh][2] * inv1, y11 = o[nh][3] * inv1;
        *(uint32_t*)(yhi + row0 * Cc + col) = packhi2(y00, y01);
        *(uint32_t*)(ylo + row0 * Cc + col) =
            packbf2(y01 - truncbf(y01), y00 - truncbf(y00));
        *(uint32_t*)(yhi + (row0 + 8) * Cc + col) = packhi2(y10, y11);
        *(uint32_t*)(ylo + (row0 + 8) * Cc + col) =
            packbf2(y11 - truncbf(y11), y10 - truncbf(y10));
    }
}

// ---------------- launch ---------------------------------------------------
extern "C" void kernel_launch(void* const* d_in, const int* in_sizes, int n_in,
                              void* d_out, int out_size)
{
    const float* x      = (const float*)d_in[0];
    const float* w_attn = (const float*)d_in[1];
    const float* b_attn = (const float*)d_in[2];
    const float* w_proj = (const float*)d_in[3];
    const float* b_proj = (const float*)d_in[4];
    float* out = (float*)d_out;

    __nv_bfloat16 *qkvhi, *qkvlo, *xhi, *xlo, *yhi, *ylo, *wahi, *walo, *wphi, *wplo;
    cudaGetSymbolAddress((void**)&qkvhi, g_qkvhi);
    cudaGetSymbolAddress((void**)&qkvlo, g_qkvlo);
    cudaGetSymbolAddress((void**)&xhi, g_xhi);
    cudaGetSymbolAddress((void**)&xlo, g_xlo);
    cudaGetSymbolAddress((void**)&yhi, g_yhi);
    cudaGetSymbolAddress((void**)&ylo, g_ylo);
    cudaGetSymbolAddress((void**)&wahi, g_wahi);
    cudaGetSymbolAddress((void**)&walo, g_walo);
    cudaGetSymbolAddress((void**)&wphi, g_wphi);
    cudaGetSymbolAddress((void**)&wplo, g_wplo);

    constexpr int GEMM_SMEM = 2 * 40960;  // 81920 -> 2 CTAs/SM
    cudaFuncSetAttribute(gemm_mma<Bb * Tt, 3 * Cc, Cc, true>,
                         cudaFuncAttributeMaxDynamicSharedMemorySize, GEMM_SMEM);
    cudaFuncSetAttribute(gemm_mma<Bb * Tt, Cc, Cc, false>,
                         cudaFuncAttributeMaxDynamicSharedMemorySize, GEMM_SMEM);
    constexpr int FLASH_SMEM = 10 * 9216;  // 92160
    cudaFuncSetAttribute(flash_mma, cudaFuncAttributeMaxDynamicSharedMemorySize,
                         FLASH_SMEM);

    {
        int n4 = (Bb * Tt * Cc) / 4;
        split_rows<<<(n4 + 255) / 256, 256>>>((const float4*)x, xhi, xlo, n4);
        split_transpose<<<dim3((3 * Cc) / 32, Cc / 32), dim3(32, 8)>>>(
            w_attn, wahi, walo, Cc, 3 * Cc);
        split_transpose<<<dim3(Cc / 32, Cc / 32), dim3(32, 8)>>>(
            w_proj, wphi, wplo, Cc, Cc);
    }

    gemm_mma<Bb * Tt, 3 * Cc, Cc, true>
        <<<dim3((3 * Cc) / 128, (Bb * Tt) / 128), 256, GEMM_SMEM>>>(
            xhi, xlo, wahi, walo, b_attn, nullptr, qkvhi, qkvlo);

    flash_mma<<<dim3(Tt / 64, Bb * Hh), 128, FLASH_SMEM>>>(qkvhi, qkvlo, yhi, ylo);

    gemm_mma<Bb * Tt, Cc, Cc, false>
        <<<dim3(Cc / 128, (Bb * Tt) / 128), 256, GEMM_SMEM>>>(
            yhi, ylo, wphi, wplo, b_proj, out, nullptr, nullptr);
}